// round 9
// baseline (speedup 1.0000x reference)
#include <cuda_runtime.h>
#include <cuda_bf16.h>
#include <cstdint>

// ---------------- problem constants ----------------
#define G    3040
#define ATM  100
#define NTOK 43
#define FS   75
#define HS   128
#define H1S  128
#define NF   512
#define NH   256
#define DH   256
#define K3ADJ (3*G)          // 9120

// ---------------- device scratch (static, allowed) ----------------
__device__ float d_xc  [G * NF];
__device__ float d_t   [G * 512];
__device__ float d_h   [G * 512];
__device__ float d_t2  [G * 512];
__device__ float d_z   [G * 512];
__device__ float d_a1  [G * 256];
__device__ float d_a2  [G * 512];
__device__ float d_z3  [G * 256];
__device__ float d_zw  [G * 256];
__device__ float d_part[3 * G * 512];
__device__ __nv_bfloat16 d_adj3p[(size_t)G * K3ADJ];
__device__ __nv_bfloat16 d_adj3n[(size_t)G * K3ADJ];
__device__ __nv_bfloat16 d_A3[(size_t)G * 1536];
__device__ __nv_bfloat16 d_B3[(size_t)9120 * 512];
__device__ int   d_is64;

// ---------------- dtype sniff for encoded_drug ----------------
__global__ void sniff_kernel(const int* __restrict__ enc) {
    __shared__ int any;
    if (threadIdx.x == 0) any = 0;
    __syncthreads();
    int seen = 0;
    for (int i = threadIdx.x; i < 4096; i += 256)
        if (enc[2 * i + 1] != 0) seen = 1;
    if (seen) atomicOr(&any, 1);
    __syncthreads();
    if (threadIdx.x == 0) d_is64 = (any == 0) ? 1 : 0;
}

// ---------------- copy x into xc[:, 0:384] ----------------
__global__ void copyx_kernel(const float* __restrict__ x) {
    int i = blockIdx.x * 256 + threadIdx.x;
    if (i < G * 384) {
        int g = i / 384, c = i - g * 384;
        d_xc[g * NF + c] = x[i];
    }
}

// ---------------- split-K reduce (+optional relu) ----------------
__global__ void reduce_kernel(float* __restrict__ out, int n, int relu) {
    int i = blockIdx.x * 256 + threadIdx.x;
    if (i < n) {
        float v = d_part[i] + d_part[i + n] + d_part[i + 2 * n];
        out[i] = relu ? fmaxf(v, 0.0f) : v;
    }
}

// ---------------- bf16 split conversions ----------------
// K-expansion: source k = 16*q + r maps to slots 48q+r, 48q+16+r, 48q+32+r.
// A slots: (hi, hi, lo)    B slots: (hi, lo, hi)
// => hi*hi + hi*lo + lo*hi  (lo*lo dropped, ~2^-18 relative)

__global__ void convA_kernel(const float* __restrict__ src, __nv_bfloat16* __restrict__ dst,
                             int M, int K, int lda) {
    long long idx = (long long)blockIdx.x * 256 + threadIdx.x;
    if (idx >= (long long)M * K) return;
    int m = (int)(idx / K), k = (int)(idx - (long long)m * K);
    float a = src[(long long)m * lda + k];
    __nv_bfloat16 hi = __float2bfloat16(a);
    __nv_bfloat16 lo = __float2bfloat16(a - __bfloat162float(hi));
    int q = k >> 4, r = k & 15;
    long long base = (long long)m * (3LL * K) + 48 * q + r;
    dst[base] = hi; dst[base + 16] = hi; dst[base + 32] = lo;
}

__global__ void convB_kernel(const float* __restrict__ src, __nv_bfloat16* __restrict__ dst,
                             int K, int N, int lds, int ldb, int trans) {
    long long idx = (long long)blockIdx.x * 256 + threadIdx.x;
    if (idx >= (long long)K * N) return;
    int k = (int)(idx / N), n = (int)(idx - (long long)k * N);
    float b = trans ? src[(long long)n * lds + k] : src[(long long)k * lds + n];
    __nv_bfloat16 hi = __float2bfloat16(b);
    __nv_bfloat16 lo = __float2bfloat16(b - __bfloat162float(hi));
    int q = k >> 4, r = k & 15;
    long long ro = 48LL * q + r;
    dst[ro * ldb + n]        = hi;
    dst[(ro + 16) * ldb + n] = lo;
    dst[(ro + 32) * ldb + n] = hi;
}

// ---------------- molecular GCN (unchanged, known-good from R5) ----------------
#define SM_ADJ  0
#define SM_W    10100
#define SM_P    26484
#define SM_Q    31988
#define SM_E    37492
#define SM_C    40720
#define SM_D    47120
#define SM_TOK  53520
#define SM_FLOATS 53624

template<int RPW, bool DOMAX>
__device__ __forceinline__ void tile_mm(const float* __restrict__ Xs, int ldx,
                                        const float* __restrict__ Ws,
                                        int K, int Mrows,
                                        float* __restrict__ Out,
                                        float4& mx)
{
    const int lane = threadIdx.x & 31;
    const int warp = threadIdx.x >> 5;
    const int r0 = warp * RPW;

    int xoff[RPW];
#pragma unroll
    for (int i = 0; i < RPW; i++) {
        int rr = r0 + i;
        if (rr >= Mrows) rr = Mrows - 1;
        xoff[i] = rr * ldx;
    }

    float acc[RPW][4];
#pragma unroll
    for (int i = 0; i < RPW; i++)
        acc[i][0] = acc[i][1] = acc[i][2] = acc[i][3] = 0.0f;

    const float* wbase = Ws + lane * 4;
#pragma unroll 4
    for (int h = 0; h < K; h++) {
        float4 wv = *(const float4*)(wbase + h * 128);
#pragma unroll
        for (int i = 0; i < RPW; i++) {
            float xv = Xs[xoff[i] + h];
            acc[i][0] = fmaf(xv, wv.x, acc[i][0]);
            acc[i][1] = fmaf(xv, wv.y, acc[i][1]);
            acc[i][2] = fmaf(xv, wv.z, acc[i][2]);
            acc[i][3] = fmaf(xv, wv.w, acc[i][3]);
        }
    }

    if (DOMAX) {
#pragma unroll
        for (int i = 0; i < RPW; i++) {
            mx.x = fmaxf(mx.x, acc[i][0]);
            mx.y = fmaxf(mx.y, acc[i][1]);
            mx.z = fmaxf(mx.z, acc[i][2]);
            mx.w = fmaxf(mx.w, acc[i][3]);
        }
    } else {
#pragma unroll
        for (int i = 0; i < RPW; i++) {
            if (r0 + i < Mrows) {
                *(float4*)(Out + (r0 + i) * 128 + lane * 4) =
                    make_float4(acc[i][0], acc[i][1], acc[i][2], acc[i][3]);
            }
        }
    }
}

__global__ void __launch_bounds__(512, 1)
mol_kernel(const float* __restrict__ mol_adj,
           const void* __restrict__ encv,
           const float* __restrict__ tok_emb,
           const float* __restrict__ Wm1,
           const float* __restrict__ Wm2)
{
    extern __shared__ float sm[];
    float* sAdj = sm + SM_ADJ;
    float* sW   = sm + SM_W;
    float* sP   = sm + SM_P;
    float* sQ   = sm + SM_Q;
    float* sE   = sm + SM_E;
    float* sC   = sm + SM_C;
    float* sD   = sm + SM_D;
    int*   stok = (int*)(sm + SM_TOK);

    const int g = blockIdx.x;
    const int tid = threadIdx.x;
    const int lane = tid & 31, warp = tid >> 5;
    const int is64 = d_is64;

    if (tid < ATM) {
        const int* e = (const int*)encv;
        stok[tid] = is64 ? e[2 * (g * ATM + tid)] : e[g * ATM + tid];
    }
    for (int idx = tid; idx < ATM * ATM; idx += 512) {
        int a = idx / ATM, b = idx - a * ATM;
        sAdj[b * 101 + a] = mol_adj[g * (ATM * ATM) + idx];
    }
    for (int idx = tid; idx < NTOK * FS; idx += 512) sE[idx] = tok_emb[idx];
    for (int idx = tid; idx < FS * HS; idx += 512) sW[idx] = Wm1[g * (FS * HS) + idx];
    for (int idx = tid; idx < ATM * 64; idx += 512) sC[idx] = 0.0f;
    __syncthreads();

    if (tid < 400) {
        int b = tid >> 2, q = tid & 3;
        const float* arow = sAdj + b * 101;
        float* crow = sC + b * 64;
        for (int a = q * 25; a < q * 25 + 25; a++)
            atomicAdd(&crow[stok[a]], arow[a]);
    }
    __syncthreads();

    float4 dummy = make_float4(0, 0, 0, 0);

    tile_mm<3, false>(sE, FS, sW, FS, NTOK, sP, dummy);
    __syncthreads();

    for (int idx = tid; idx < HS * H1S; idx += 512) sW[idx] = Wm2[g * (HS * H1S) + idx];
    __syncthreads();

    tile_mm<3, false>(sP, 128, sW, HS, NTOK, sQ, dummy);
    __syncthreads();

    {
        const int r0 = warp * 7;
        float ac0[7], ac1[7];
#pragma unroll
        for (int i = 0; i < 7; i++) { ac0[i] = 0.0f; ac1[i] = 0.0f; }
        int roff[7];
#pragma unroll
        for (int i = 0; i < 7; i++) {
            int rr = r0 + i; if (rr >= ATM) rr = ATM - 1;
            roff[i] = rr * 101;
        }
        for (int a = 0; a < ATM; a++) {
            float c0 = sC[a * 64 + lane];
            float c1 = sC[a * 64 + 32 + lane];
#pragma unroll
            for (int i = 0; i < 7; i++) {
                float av = sAdj[roff[i] + a];
                ac0[i] = fmaf(av, c0, ac0[i]);
                ac1[i] = fmaf(av, c1, ac1[i]);
            }
        }
#pragma unroll
        for (int i = 0; i < 7; i++) {
            if (r0 + i < ATM) {
                sD[(r0 + i) * 64 + lane] = ac0[i];
                sD[(r0 + i) * 64 + 32 + lane] = ac1[i];
            }
        }
    }
    __syncthreads();

    float4 mx = make_float4(-3.4e38f, -3.4e38f, -3.4e38f, -3.4e38f);
    tile_mm<7, true>(sD, 64, sQ, NTOK, ATM, nullptr, mx);
    __syncthreads();

    *(float4*)(sW + warp * 128 + lane * 4) = mx;
    __syncthreads();
    if (tid < 128) {
        float m = sW[tid];
#pragma unroll
        for (int w = 1; w < 16; w++) m = fmaxf(m, sW[w * 128 + tid]);
        d_xc[g * NF + 384 + tid] = m;
    }
}

// ---------------- bf16 tensor-core GEMM (mma.sync m16n8k16) ----------------
// Conservative: no cp.async, no ldmatrix. Register-prefetched vectorized loads;
// fragments read directly from smem in mma layout.
// A staged [row][k] pitch 40.  B staged TRANSPOSED [n][k] pitch 40.
// Tiles 128x128x32, 256 threads, 8 warps (2x4), each warp 64x32.
struct TG {
    const __nv_bfloat16* A; const __nv_bfloat16* B; float* C;
    int M, N, lda, ldb, ldc;
    int relu, kspl, Kc;
    long long pstride;
};

#define TPITCH 40                 // bf16 units per staged row (80 B)
#define TSTG   (128 * TPITCH)     // 5120 per operand

__global__ void __launch_bounds__(256, 2)
tgemm(TG P0, TG P1)
{
    __shared__ __nv_bfloat16 As[TSTG];
    __shared__ __nv_bfloat16 Bs[TSTG];

    const int z = blockIdx.z;
    TG p = (z >= P0.kspl) ? P1 : P0;
    const int slice = (z >= P0.kspl) ? (z - P0.kspl) : z;
    const int k0 = slice * p.Kc;
    const int niter = p.Kc >> 5;
    float* Cp = p.C + (long long)slice * p.pstride;

    const int t = threadIdx.x;
    const int m0 = blockIdx.y * 128, n0 = blockIdx.x * 128;

    // A staging: thread -> row = t>>1, k-halfpanel = (t&1)*16.
    // TWO float4 loads per thread (k base and base+8) => FULL 128x32 coverage.
    const int ar  = t >> 1;
    const int akq = (t & 1) * 16;
    const long long aoff = (long long)min(m0 + ar, p.M - 1) * p.lda;

    // B staging (transpose on store): bk = t>>3 (0..31), bn0 = (t&7)*16;
    // two float4 loads cover 16 n-columns per thread => FULL 32x128 coverage.
    const int bk  = t >> 3;
    const int bn0 = (t & 7) * 16;
    const int bgn0 = min(n0 + bn0, p.N - 8);
    const int bgn1 = min(n0 + bn0 + 8, p.N - 8);

    float acc[4][4][4];
#pragma unroll
    for (int i = 0; i < 4; i++)
#pragma unroll
        for (int j = 0; j < 4; j++)
#pragma unroll
            for (int q = 0; q < 4; q++) acc[i][j][q] = 0.0f;

    const int lane = t & 31, warp = t >> 5;
    const int wm = warp >> 2, wn = warp & 3;
    const int grp = lane >> 2;       // groupID 0..7
    const int tid4 = lane & 3;       // threadID-in-group

    // prefetch first panel
    float4 ra0, ra1, rb0, rb1;
    {
        ra0 = *(const float4*)(p.A + aoff + k0 + akq);
        ra1 = *(const float4*)(p.A + aoff + k0 + akq + 8);
        const __nv_bfloat16* bg = p.B + (long long)(k0 + bk) * p.ldb;
        rb0 = *(const float4*)(bg + bgn0);
        rb1 = *(const float4*)(bg + bgn1);
    }

    for (int it = 0; it < niter; it++) {
        // store staged panel (A: both chunks; B: transpose scatter)
        *(float4*)(As + ar * TPITCH + akq)     = ra0;
        *(float4*)(As + ar * TPITCH + akq + 8) = ra1;
        {
            const __nv_bfloat16* e0 = (const __nv_bfloat16*)&rb0;
            const __nv_bfloat16* e1 = (const __nv_bfloat16*)&rb1;
#pragma unroll
            for (int j = 0; j < 8; j++) {
                Bs[(bn0 + j) * TPITCH + bk]     = e0[j];
                Bs[(bn0 + 8 + j) * TPITCH + bk] = e1[j];
            }
        }
        __syncthreads();

        // prefetch next panel
        if (it + 1 < niter) {
            int kn = k0 + (it + 1) * 32;
            ra0 = *(const float4*)(p.A + aoff + kn + akq);
            ra1 = *(const float4*)(p.A + aoff + kn + akq + 8);
            const __nv_bfloat16* bg = p.B + (long long)(kn + bk) * p.ldb;
            rb0 = *(const float4*)(bg + bgn0);
            rb1 = *(const float4*)(bg + bgn1);
        }

#pragma unroll
        for (int kk = 0; kk < 32; kk += 16) {
            // A fragments (row-major): a0=(row grp, k tid4*2), a1=(row grp+8, k),
            // a2=(row grp, k+8), a3=(row grp+8, k+8)
            uint32_t afr[4][4];
#pragma unroll
            for (int mt = 0; mt < 4; mt++) {
                const __nv_bfloat16* a0 = As + (wm * 64 + mt * 16 + grp) * TPITCH + kk + tid4 * 2;
                const __nv_bfloat16* a1 = a0 + 8 * TPITCH;
                afr[mt][0] = *(const uint32_t*)(a0);
                afr[mt][1] = *(const uint32_t*)(a1);
                afr[mt][2] = *(const uint32_t*)(a0 + 8);
                afr[mt][3] = *(const uint32_t*)(a1 + 8);
            }
            // B fragments (col-major): b0=(k tid4*2, n grp), b1=(k+8, n grp)
            uint32_t bfr[4][2];
#pragma unroll
            for (int nt = 0; nt < 4; nt++) {
                const __nv_bfloat16* b0 = Bs + (wn * 32 + nt * 8 + grp) * TPITCH + kk + tid4 * 2;
                bfr[nt][0] = *(const uint32_t*)(b0);
                bfr[nt][1] = *(const uint32_t*)(b0 + 8);
            }
#pragma unroll
            for (int mt = 0; mt < 4; mt++)
#pragma unroll
                for (int nt = 0; nt < 4; nt++)
                    asm volatile(
                        "mma.sync.aligned.m16n8k16.row.col.f32.bf16.bf16.f32 "
                        "{%0,%1,%2,%3}, {%4,%5,%6,%7}, {%8,%9}, {%0,%1,%2,%3};\n"
                        : "+f"(acc[mt][nt][0]), "+f"(acc[mt][nt][1]),
                          "+f"(acc[mt][nt][2]), "+f"(acc[mt][nt][3])
                        : "r"(afr[mt][0]), "r"(afr[mt][1]),
                          "r"(afr[mt][2]), "r"(afr[mt][3]),
                          "r"(bfr[nt][0]), "r"(bfr[nt][1]));
        }
        __syncthreads();
    }

    // epilogue
    const int cr = m0 + wm * 64 + grp;
    const int cc = n0 + wn * 32 + tid4 * 2;
#pragma unroll
    for (int mt = 0; mt < 4; mt++) {
        int r0 = cr + mt * 16;
#pragma unroll
        for (int nt = 0; nt < 4; nt++) {
            int c0 = cc + nt * 8;
            if (c0 < p.N) {
                float v0 = acc[mt][nt][0], v1 = acc[mt][nt][1];
                float v2 = acc[mt][nt][2], v3 = acc[mt][nt][3];
                if (p.relu) {
                    v0 = fmaxf(v0, 0.0f); v1 = fmaxf(v1, 0.0f);
                    v2 = fmaxf(v2, 0.0f); v3 = fmaxf(v3, 0.0f);
                }
                if (r0 < p.M) {
                    Cp[(long long)r0 * p.ldc + c0]     = v0;
                    Cp[(long long)r0 * p.ldc + c0 + 1] = v1;
                }
                if (r0 + 8 < p.M) {
                    Cp[(long long)(r0 + 8) * p.ldc + c0]     = v2;
                    Cp[(long long)(r0 + 8) * p.ldc + c0 + 1] = v3;
                }
            }
        }
    }
}

// ---------------- host helpers ----------------
static TG mkt(const __nv_bfloat16* A, int lda, const __nv_bfloat16* B, int ldb,
              float* C, int ldc, int M, int N, int relu,
              int kspl, int Kc, long long pstride)
{
    TG p; p.A = A; p.B = B; p.C = C; p.M = M; p.N = N;
    p.lda = lda; p.ldb = ldb; p.ldc = ldc; p.relu = relu;
    p.kspl = kspl; p.Kc = Kc; p.pstride = pstride;
    return p;
}

static void tlaunch(const TG& p0, const TG& p1, int nbranch)
{
    dim3 grid((p0.N + 127) / 128, (p0.M + 127) / 128, nbranch * p0.kspl);
    tgemm<<<grid, 256>>>(p0, p1);
}

static void convA(const float* src, __nv_bfloat16* dst, int M, int K, int lda) {
    long long n = (long long)M * K;
    convA_kernel<<<(int)((n + 255) / 256), 256>>>(src, dst, M, K, lda);
}
static void convB(const float* src, __nv_bfloat16* dst, int K, int N,
                  int lds, int ldb, int trans) {
    long long n = (long long)K * N;
    convB_kernel<<<(int)((n + 255) / 256), 256>>>(src, dst, K, N, lds, ldb, trans);
}

extern "C" void kernel_launch(void* const* d_in, const int* in_sizes, int n_in,
                              void* d_out, int out_size)
{
    const float* x       = (const float*)d_in[0];
    const float* adj_pos = (const float*)d_in[1];
    const float* adj_neg = (const float*)d_in[2];
    const float* mol_adj = (const float*)d_in[3];
    const void*  enc     = d_in[4];
    const float* tok_emb = (const float*)d_in[5];
    const float* Wm1     = (const float*)d_in[6];
    const float* Wm2     = (const float*)d_in[7];
    const float* Wp1     = (const float*)d_in[8];
    const float* Wp2     = (const float*)d_in[9];
    const float* Wn1     = (const float*)d_in[10];
    const float* Wn2     = (const float*)d_in[11];
    const float* Wd1     = (const float*)d_in[12];
    const float* Wd2     = (const float*)d_in[13];
    const float* Wd3     = (const float*)d_in[14];
    const float* Wdec    = (const float*)d_in[15];
    float* out = (float*)d_out;

    (void)in_sizes; (void)n_in; (void)out_size;

    cudaFuncSetAttribute(mol_kernel, cudaFuncAttributeMaxDynamicSharedMemorySize,
                         SM_FLOATS * sizeof(float));

    float *xc, *t, *h, *t2, *zb, *a1, *a2, *z3, *zw, *part;
    __nv_bfloat16 *adj3p, *adj3n, *A3, *B3;
    cudaGetSymbolAddress((void**)&xc,    d_xc);
    cudaGetSymbolAddress((void**)&t,     d_t);
    cudaGetSymbolAddress((void**)&h,     d_h);
    cudaGetSymbolAddress((void**)&t2,    d_t2);
    cudaGetSymbolAddress((void**)&zb,    d_z);
    cudaGetSymbolAddress((void**)&a1,    d_a1);
    cudaGetSymbolAddress((void**)&a2,    d_a2);
    cudaGetSymbolAddress((void**)&z3,    d_z3);
    cudaGetSymbolAddress((void**)&zw,    d_zw);
    cudaGetSymbolAddress((void**)&part,  d_part);
    cudaGetSymbolAddress((void**)&adj3p, d_adj3p);
    cudaGetSymbolAddress((void**)&adj3n, d_adj3n);
    cudaGetSymbolAddress((void**)&A3,    d_A3);
    cudaGetSymbolAddress((void**)&B3,    d_B3);

    const int NE = G * 512;
    const long long B3HALF = (long long)9120 * 256;

    // 0) sniff + xc prefix + adjacency bf16 split (reused by steps 5 & 7)
    sniff_kernel<<<1, 256>>>((const int*)enc);
    copyx_kernel<<<(G * 384 + 255) / 256, 256>>>(x);
    convA(adj_pos, adj3p, G, G, G);
    convA(adj_neg, adj3n, G, G, G);

    // 3) molecular GCN -> xc[:, 384:512]
    mol_kernel<<<G, 512, SM_FLOATS * sizeof(float)>>>(mol_adj, enc, tok_emb, Wm1, Wm2);

    // 4) t = xc @ [Wp1 | Wn1]      (K=512 -> Keff 1536)
    convA(xc, A3, G, 512, 512);
    convB(Wp1, B3, 512, 256, 256, 256, 0);
    convB(Wn1, B3 + (long long)1536 * 256, 512, 256, 256, 256, 0);
    tlaunch(mkt(A3, 1536, B3, 256, t, 512, G, 256, 0, 1, 1536, 0),
            mkt(A3, 1536, B3 + (long long)1536 * 256, 256, t + 256, 512, G, 256, 0, 1, 1536, 0), 2);

    // 5) h = relu(adj @ t)         (Keff 9120, split-K 3)
    convB(t,       B3,          G, 256, 512, 256, 0);
    convB(t + 256, B3 + B3HALF, G, 256, 512, 256, 0);
    tlaunch(mkt(adj3p, K3ADJ, B3,          256, part,       512, G, 256, 0, 3, 3040, NE),
            mkt(adj3n, K3ADJ, B3 + B3HALF, 256, part + 256, 512, G, 256, 0, 3, 3040, NE), 2);
    reduce_kernel<<<(NE + 255) / 256, 256>>>(h, NE, 1);

    // 6) t2 = h @ [Wp2 | Wn2]      (Keff 768)
    convA(h,       A3,                      G, 256, 512);
    convA(h + 256, A3 + (long long)G * 768, G, 256, 512);
    convB(Wp2, B3,                        256, 256, 256, 256, 0);
    convB(Wn2, B3 + (long long)768 * 256, 256, 256, 256, 256, 0);
    tlaunch(mkt(A3,                      768, B3,                        256, t2,       512, G, 256, 0, 1, 768, 0),
            mkt(A3 + (long long)G * 768, 768, B3 + (long long)768 * 256, 256, t2 + 256, 512, G, 256, 0, 1, 768, 0), 2);

    // 7) z = adj @ t2
    convB(t2,       B3,          G, 256, 512, 256, 0);
    convB(t2 + 256, B3 + B3HALF, G, 256, 512, 256, 0);
    tlaunch(mkt(adj3p, K3ADJ, B3,          256, part,       512, G, 256, 0, 3, 3040, NE),
            mkt(adj3n, K3ADJ, B3 + B3HALF, 256, part + 256, 512, G, 256, 0, 3, 3040, NE), 2);
    reduce_kernel<<<(NE + 255) / 256, 256>>>(zb, NE, 0);

    // 8) a1 = relu(z @ Wd1)        (Keff 1536)
    convA(zb, A3, G, 512, 512);
    convB(Wd1, B3, 512, 256, 256, 256, 0);
    {
        TG p = mkt(A3, 1536, B3, 256, a1, 256, G, 256, 1, 1, 1536, 0);
        tlaunch(p, p, 1);
    }

    // 9) a2 = relu(a1 @ Wd2)       (Keff 768, N=512)
    convA(a1, A3, G, 256, 256);
    convB(Wd2, B3, 256, 512, 512, 512, 0);
    {
        TG p = mkt(A3, 768, B3, 512, a2, 512, G, 512, 1, 1, 768, 0);
        tlaunch(p, p, 1);
    }

    // 10) z3 = a2 @ Wd3            (Keff 1536)
    convA(a2, A3, G, 512, 512);
    convB(Wd3, B3, 512, 256, 256, 256, 0);
    {
        TG p = mkt(A3, 1536, B3, 256, z3, 256, G, 256, 0, 1, 1536, 0);
        tlaunch(p, p, 1);
    }

    // 11) zw = z3 @ Wdec           (Keff 768)
    convA(z3, A3, G, 256, 256);
    convB(Wdec, B3, 256, 256, 256, 256, 0);
    {
        TG p = mkt(A3, 768, B3, 256, zw, 256, G, 256, 0, 1, 768, 0);
        tlaunch(p, p, 1);
    }

    // 12) out = zw @ z3^T          (Keff 768, N=3040)
    convA(zw, A3, G, 256, 256);
    convB(z3, B3, 256, G, 256, G, 1);
    {
        TG p = mkt(A3, 768, B3, G, out, G, G, G, 0, 1, 768, 0);
        tlaunch(p, p, 1);
    }
}

// round 10
// speedup vs baseline: 1.1540x; 1.1540x over previous
#include <cuda_runtime.h>
#include <cuda_bf16.h>
#include <cstdint>

// ---------------- problem constants ----------------
#define G    3040
#define ATM  100
#define NTOK 43
#define FS   75
#define HS   128
#define H1S  128
#define NF   512
#define NH   256
#define DH   256
#define K3ADJ (3*G)          // 9120

// ---------------- device scratch (static, allowed) ----------------
__device__ float d_xc  [G * NF];
__device__ float d_t   [G * 512];
__device__ float d_h   [G * 512];
__device__ float d_t2  [G * 512];
__device__ float d_z   [G * 512];
__device__ float d_a1  [G * 256];
__device__ float d_a2  [G * 512];
__device__ float d_z3  [G * 256];
__device__ float d_zw  [G * 256];
__device__ float d_part[3 * G * 512];
__device__ __nv_bfloat16 d_adj3p[(size_t)G * K3ADJ];
__device__ __nv_bfloat16 d_adj3n[(size_t)G * K3ADJ];
__device__ __nv_bfloat16 d_A3[(size_t)G * 1536];
__device__ __nv_bfloat16 d_B3[(size_t)9120 * 512];
__device__ int   d_is64;

// ---------------- dtype sniff for encoded_drug ----------------
__global__ void sniff_kernel(const int* __restrict__ enc) {
    __shared__ int any;
    if (threadIdx.x == 0) any = 0;
    __syncthreads();
    int seen = 0;
    for (int i = threadIdx.x; i < 4096; i += 256)
        if (enc[2 * i + 1] != 0) seen = 1;
    if (seen) atomicOr(&any, 1);
    __syncthreads();
    if (threadIdx.x == 0) d_is64 = (any == 0) ? 1 : 0;
}

// ---------------- copy x into xc[:, 0:384] ----------------
__global__ void copyx_kernel(const float* __restrict__ x) {
    int i = blockIdx.x * 256 + threadIdx.x;
    if (i < G * 384) {
        int g = i / 384, c = i - g * 384;
        d_xc[g * NF + c] = x[i];
    }
}

// ---------------- split-K reduce (+optional relu) ----------------
__global__ void reduce_kernel(float* __restrict__ out, int n, int relu) {
    int i = blockIdx.x * 256 + threadIdx.x;
    if (i < n) {
        float v = d_part[i] + d_part[i + n] + d_part[i + 2 * n];
        out[i] = relu ? fmaxf(v, 0.0f) : v;
    }
}

// ---------------- bf16 split conversions ----------------
// K-expansion: source k = 16*q + r maps to slots 48q+r, 48q+16+r, 48q+32+r.
// A slots: (hi, hi, lo)    B slots: (hi, lo, hi)
// => hi*hi + hi*lo + lo*hi  (lo*lo dropped, ~2^-18 relative)
// A3 layout: [M][Keff] row-major.   B3 layout: [N][Keff] K-MAJOR (transposed).

__global__ void convA_kernel(const float* __restrict__ src, __nv_bfloat16* __restrict__ dst,
                             int M, int K, int lda) {
    long long idx = (long long)blockIdx.x * 256 + threadIdx.x;
    if (idx >= (long long)M * K) return;
    int m = (int)(idx / K), k = (int)(idx - (long long)m * K);
    float a = src[(long long)m * lda + k];
    __nv_bfloat16 hi = __float2bfloat16(a);
    __nv_bfloat16 lo = __float2bfloat16(a - __bfloat162float(hi));
    int q = k >> 4, r = k & 15;
    long long base = (long long)m * (3LL * K) + 48 * q + r;
    dst[base] = hi; dst[base + 16] = hi; dst[base + 32] = lo;
}

// dst[n][slot(k)]  with row pitch 3K
__global__ void convB_kernel(const float* __restrict__ src, __nv_bfloat16* __restrict__ dst,
                             int K, int N, int lds, int trans) {
    long long idx = (long long)blockIdx.x * 256 + threadIdx.x;
    if (idx >= (long long)K * N) return;
    int k = (int)(idx / N), n = (int)(idx - (long long)k * N);
    float b = trans ? src[(long long)n * lds + k] : src[(long long)k * lds + n];
    __nv_bfloat16 hi = __float2bfloat16(b);
    __nv_bfloat16 lo = __float2bfloat16(b - __bfloat162float(hi));
    int q = k >> 4, r = k & 15;
    long long base = (long long)n * (3LL * K) + 48 * q + r;
    dst[base] = hi; dst[base + 16] = lo; dst[base + 32] = hi;
}

// ---------------- molecular GCN (unchanged, known-good from R5) ----------------
#define SM_ADJ  0
#define SM_W    10100
#define SM_P    26484
#define SM_Q    31988
#define SM_E    37492
#define SM_C    40720
#define SM_D    47120
#define SM_TOK  53520
#define SM_FLOATS 53624

template<int RPW, bool DOMAX>
__device__ __forceinline__ void tile_mm(const float* __restrict__ Xs, int ldx,
                                        const float* __restrict__ Ws,
                                        int K, int Mrows,
                                        float* __restrict__ Out,
                                        float4& mx)
{
    const int lane = threadIdx.x & 31;
    const int warp = threadIdx.x >> 5;
    const int r0 = warp * RPW;

    int xoff[RPW];
#pragma unroll
    for (int i = 0; i < RPW; i++) {
        int rr = r0 + i;
        if (rr >= Mrows) rr = Mrows - 1;
        xoff[i] = rr * ldx;
    }

    float acc[RPW][4];
#pragma unroll
    for (int i = 0; i < RPW; i++)
        acc[i][0] = acc[i][1] = acc[i][2] = acc[i][3] = 0.0f;

    const float* wbase = Ws + lane * 4;
#pragma unroll 4
    for (int h = 0; h < K; h++) {
        float4 wv = *(const float4*)(wbase + h * 128);
#pragma unroll
        for (int i = 0; i < RPW; i++) {
            float xv = Xs[xoff[i] + h];
            acc[i][0] = fmaf(xv, wv.x, acc[i][0]);
            acc[i][1] = fmaf(xv, wv.y, acc[i][1]);
            acc[i][2] = fmaf(xv, wv.z, acc[i][2]);
            acc[i][3] = fmaf(xv, wv.w, acc[i][3]);
        }
    }

    if (DOMAX) {
#pragma unroll
        for (int i = 0; i < RPW; i++) {
            mx.x = fmaxf(mx.x, acc[i][0]);
            mx.y = fmaxf(mx.y, acc[i][1]);
            mx.z = fmaxf(mx.z, acc[i][2]);
            mx.w = fmaxf(mx.w, acc[i][3]);
        }
    } else {
#pragma unroll
        for (int i = 0; i < RPW; i++) {
            if (r0 + i < Mrows) {
                *(float4*)(Out + (r0 + i) * 128 + lane * 4) =
                    make_float4(acc[i][0], acc[i][1], acc[i][2], acc[i][3]);
            }
        }
    }
}

__global__ void __launch_bounds__(512, 1)
mol_kernel(const float* __restrict__ mol_adj,
           const void* __restrict__ encv,
           const float* __restrict__ tok_emb,
           const float* __restrict__ Wm1,
           const float* __restrict__ Wm2)
{
    extern __shared__ float sm[];
    float* sAdj = sm + SM_ADJ;
    float* sW   = sm + SM_W;
    float* sP   = sm + SM_P;
    float* sQ   = sm + SM_Q;
    float* sE   = sm + SM_E;
    float* sC   = sm + SM_C;
    float* sD   = sm + SM_D;
    int*   stok = (int*)(sm + SM_TOK);

    const int g = blockIdx.x;
    const int tid = threadIdx.x;
    const int lane = tid & 31, warp = tid >> 5;
    const int is64 = d_is64;

    if (tid < ATM) {
        const int* e = (const int*)encv;
        stok[tid] = is64 ? e[2 * (g * ATM + tid)] : e[g * ATM + tid];
    }
    for (int idx = tid; idx < ATM * ATM; idx += 512) {
        int a = idx / ATM, b = idx - a * ATM;
        sAdj[b * 101 + a] = mol_adj[g * (ATM * ATM) + idx];
    }
    for (int idx = tid; idx < NTOK * FS; idx += 512) sE[idx] = tok_emb[idx];
    for (int idx = tid; idx < FS * HS; idx += 512) sW[idx] = Wm1[g * (FS * HS) + idx];
    for (int idx = tid; idx < ATM * 64; idx += 512) sC[idx] = 0.0f;
    __syncthreads();

    if (tid < 400) {
        int b = tid >> 2, q = tid & 3;
        const float* arow = sAdj + b * 101;
        float* crow = sC + b * 64;
        for (int a = q * 25; a < q * 25 + 25; a++)
            atomicAdd(&crow[stok[a]], arow[a]);
    }
    __syncthreads();

    float4 dummy = make_float4(0, 0, 0, 0);

    tile_mm<3, false>(sE, FS, sW, FS, NTOK, sP, dummy);
    __syncthreads();

    for (int idx = tid; idx < HS * H1S; idx += 512) sW[idx] = Wm2[g * (HS * H1S) + idx];
    __syncthreads();

    tile_mm<3, false>(sP, 128, sW, HS, NTOK, sQ, dummy);
    __syncthreads();

    {
        const int r0 = warp * 7;
        float ac0[7], ac1[7];
#pragma unroll
        for (int i = 0; i < 7; i++) { ac0[i] = 0.0f; ac1[i] = 0.0f; }
        int roff[7];
#pragma unroll
        for (int i = 0; i < 7; i++) {
            int rr = r0 + i; if (rr >= ATM) rr = ATM - 1;
            roff[i] = rr * 101;
        }
        for (int a = 0; a < ATM; a++) {
            float c0 = sC[a * 64 + lane];
            float c1 = sC[a * 64 + 32 + lane];
#pragma unroll
            for (int i = 0; i < 7; i++) {
                float av = sAdj[roff[i] + a];
                ac0[i] = fmaf(av, c0, ac0[i]);
                ac1[i] = fmaf(av, c1, ac1[i]);
            }
        }
#pragma unroll
        for (int i = 0; i < 7; i++) {
            if (r0 + i < ATM) {
                sD[(r0 + i) * 64 + lane] = ac0[i];
                sD[(r0 + i) * 64 + 32 + lane] = ac1[i];
            }
        }
    }
    __syncthreads();

    float4 mx = make_float4(-3.4e38f, -3.4e38f, -3.4e38f, -3.4e38f);
    tile_mm<7, true>(sD, 64, sQ, NTOK, ATM, nullptr, mx);
    __syncthreads();

    *(float4*)(sW + warp * 128 + lane * 4) = mx;
    __syncthreads();
    if (tid < 128) {
        float m = sW[tid];
#pragma unroll
        for (int w = 1; w < 16; w++) m = fmaxf(m, sW[w * 128 + tid]);
        d_xc[g * NF + 384 + tid] = m;
    }
}

// ---------------- bf16 tensor-core GEMM (mma.sync m16n8k16) ----------------
// A [M][Keff] row-major, B [N][Keff] K-major (both staged identically).
// ldmatrix.x4 fragment loads (conflict-free at pitch 40).
// Tiles 128x128x32, 256 threads, 8 warps (2x4), each warp 64x32.
struct TG {
    const __nv_bfloat16* A; const __nv_bfloat16* B; float* C;
    int M, N, lda, ldb, ldc;      // lda/ldb in bf16 units (row pitch = Keff)
    int relu, kspl, Kc;
    long long pstride;
};

#define TPITCH 40                 // bf16 units per staged row (80 B)
#define TSTG   (128 * TPITCH)     // 5120 per operand

__global__ void __launch_bounds__(256, 2)
tgemm(TG P0, TG P1)
{
    __shared__ __nv_bfloat16 As[TSTG];
    __shared__ __nv_bfloat16 Bs[TSTG];

    const int z = blockIdx.z;
    TG p = (z >= P0.kspl) ? P1 : P0;
    const int slice = (z >= P0.kspl) ? (z - P0.kspl) : z;
    const int k0 = slice * p.Kc;
    const int niter = p.Kc >> 5;
    float* Cp = p.C + (long long)slice * p.pstride;

    const int t = threadIdx.x;
    const int m0 = blockIdx.y * 128, n0 = blockIdx.x * 128;

    // staging maps (identical for A and B): row = t>>1, k-half = (t&1)*16,
    // two float4 per operand per thread -> full 128x32 coverage.
    const int sr  = t >> 1;
    const int skq = (t & 1) * 16;
    const long long aoff = (long long)min(m0 + sr, p.M - 1) * p.lda;
    const long long boff = (long long)min(n0 + sr, p.N - 1) * p.ldb;

    float acc[4][4][4];
#pragma unroll
    for (int i = 0; i < 4; i++)
#pragma unroll
        for (int j = 0; j < 4; j++)
#pragma unroll
            for (int q = 0; q < 4; q++) acc[i][j][q] = 0.0f;

    const int lane = t & 31, warp = t >> 5;
    const int wm = warp >> 2, wn = warp & 3;

    // ldmatrix address lanes:
    // A: row = lane&15, k-half = (lane>>4)*8   (mats: mlo/klo, mhi/klo, mlo/khi, mhi/khi)
    const int arow = (lane & 15);
    const int akh  = ((lane >> 4) & 1) * 8;
    // B: n = ((lane>>4)&1)*8 + (lane&7), k-half = ((lane>>3)&1)*8
    //    (mats: nlo/klo, nlo/khi, nhi/klo, nhi/khi)
    const int brow = ((lane >> 4) & 1) * 8 + (lane & 7);
    const int bkh  = ((lane >> 3) & 1) * 8;

    // prefetch first panel
    float4 ra0, ra1, rb0, rb1;
    {
        ra0 = *(const float4*)(p.A + aoff + k0 + skq);
        ra1 = *(const float4*)(p.A + aoff + k0 + skq + 8);
        rb0 = *(const float4*)(p.B + boff + k0 + skq);
        rb1 = *(const float4*)(p.B + boff + k0 + skq + 8);
    }

    for (int it = 0; it < niter; it++) {
        *(float4*)(As + sr * TPITCH + skq)     = ra0;
        *(float4*)(As + sr * TPITCH + skq + 8) = ra1;
        *(float4*)(Bs + sr * TPITCH + skq)     = rb0;
        *(float4*)(Bs + sr * TPITCH + skq + 8) = rb1;
        __syncthreads();

        if (it + 1 < niter) {
            int kn = k0 + (it + 1) * 32;
            ra0 = *(const float4*)(p.A + aoff + kn + skq);
            ra1 = *(const float4*)(p.A + aoff + kn + skq + 8);
            rb0 = *(const float4*)(p.B + boff + kn + skq);
            rb1 = *(const float4*)(p.B + boff + kn + skq + 8);
        }

#pragma unroll
        for (int kk = 0; kk < 32; kk += 16) {
            uint32_t afr[4][4];
#pragma unroll
            for (int mt = 0; mt < 4; mt++) {
                const __nv_bfloat16* aptr =
                    As + (wm * 64 + mt * 16 + arow) * TPITCH + kk + akh;
                uint32_t sa = (uint32_t)__cvta_generic_to_shared(aptr);
                asm volatile(
                    "ldmatrix.sync.aligned.m8n8.x4.shared.b16 {%0,%1,%2,%3}, [%4];\n"
                    : "=r"(afr[mt][0]), "=r"(afr[mt][1]),
                      "=r"(afr[mt][2]), "=r"(afr[mt][3]) : "r"(sa));
            }
            uint32_t bfr[4][2];
#pragma unroll
            for (int ntp = 0; ntp < 2; ntp++) {
                const __nv_bfloat16* bptr =
                    Bs + (wn * 32 + ntp * 16 + brow) * TPITCH + kk + bkh;
                uint32_t sb = (uint32_t)__cvta_generic_to_shared(bptr);
                uint32_t r0, r1, r2, r3;
                asm volatile(
                    "ldmatrix.sync.aligned.m8n8.x4.shared.b16 {%0,%1,%2,%3}, [%4];\n"
                    : "=r"(r0), "=r"(r1), "=r"(r2), "=r"(r3) : "r"(sb));
                bfr[ntp * 2][0] = r0;     bfr[ntp * 2][1] = r1;
                bfr[ntp * 2 + 1][0] = r2; bfr[ntp * 2 + 1][1] = r3;
            }
#pragma unroll
            for (int mt = 0; mt < 4; mt++)
#pragma unroll
                for (int nt = 0; nt < 4; nt++)
                    asm volatile(
                        "mma.sync.aligned.m16n8k16.row.col.f32.bf16.bf16.f32 "
                        "{%0,%1,%2,%3}, {%4,%5,%6,%7}, {%8,%9}, {%0,%1,%2,%3};\n"
                        : "+f"(acc[mt][nt][0]), "+f"(acc[mt][nt][1]),
                          "+f"(acc[mt][nt][2]), "+f"(acc[mt][nt][3])
                        : "r"(afr[mt][0]), "r"(afr[mt][1]),
                          "r"(afr[mt][2]), "r"(afr[mt][3]),
                          "r"(bfr[nt][0]), "r"(bfr[nt][1]));
        }
        __syncthreads();
    }

    // epilogue
    const int grp = lane >> 2, tid4 = lane & 3;
    const int cr = m0 + wm * 64 + grp;
    const int cc = n0 + wn * 32 + tid4 * 2;
#pragma unroll
    for (int mt = 0; mt < 4; mt++) {
        int r0 = cr + mt * 16;
#pragma unroll
        for (int nt = 0; nt < 4; nt++) {
            int c0 = cc + nt * 8;
            if (c0 < p.N) {
                float v0 = acc[mt][nt][0], v1 = acc[mt][nt][1];
                float v2 = acc[mt][nt][2], v3 = acc[mt][nt][3];
                if (p.relu) {
                    v0 = fmaxf(v0, 0.0f); v1 = fmaxf(v1, 0.0f);
                    v2 = fmaxf(v2, 0.0f); v3 = fmaxf(v3, 0.0f);
                }
                if (r0 < p.M) {
                    Cp[(long long)r0 * p.ldc + c0]     = v0;
                    Cp[(long long)r0 * p.ldc + c0 + 1] = v1;
                }
                if (r0 + 8 < p.M) {
                    Cp[(long long)(r0 + 8) * p.ldc + c0]     = v2;
                    Cp[(long long)(r0 + 8) * p.ldc + c0 + 1] = v3;
                }
            }
        }
    }
}

// ---------------- host helpers ----------------
static TG mkt(const __nv_bfloat16* A, int lda, const __nv_bfloat16* B, int ldb,
              float* C, int ldc, int M, int N, int relu,
              int kspl, int Kc, long long pstride)
{
    TG p; p.A = A; p.B = B; p.C = C; p.M = M; p.N = N;
    p.lda = lda; p.ldb = ldb; p.ldc = ldc; p.relu = relu;
    p.kspl = kspl; p.Kc = Kc; p.pstride = pstride;
    return p;
}

static void tlaunch(const TG& p0, const TG& p1, int nbranch)
{
    dim3 grid((p0.N + 127) / 128, (p0.M + 127) / 128, nbranch * p0.kspl);
    tgemm<<<grid, 256>>>(p0, p1);
}

static void convA(const float* src, __nv_bfloat16* dst, int M, int K, int lda) {
    long long n = (long long)M * K;
    convA_kernel<<<(int)((n + 255) / 256), 256>>>(src, dst, M, K, lda);
}
static void convB(const float* src, __nv_bfloat16* dst, int K, int N,
                  int lds, int trans) {
    long long n = (long long)K * N;
    convB_kernel<<<(int)((n + 255) / 256), 256>>>(src, dst, K, N, lds, trans);
}

extern "C" void kernel_launch(void* const* d_in, const int* in_sizes, int n_in,
                              void* d_out, int out_size)
{
    const float* x       = (const float*)d_in[0];
    const float* adj_pos = (const float*)d_in[1];
    const float* adj_neg = (const float*)d_in[2];
    const float* mol_adj = (const float*)d_in[3];
    const void*  enc     = d_in[4];
    const float* tok_emb = (const float*)d_in[5];
    const float* Wm1     = (const float*)d_in[6];
    const float* Wm2     = (const float*)d_in[7];
    const float* Wp1     = (const float*)d_in[8];
    const float* Wp2     = (const float*)d_in[9];
    const float* Wn1     = (const float*)d_in[10];
    const float* Wn2     = (const float*)d_in[11];
    const float* Wd1     = (const float*)d_in[12];
    const float* Wd2     = (const float*)d_in[13];
    const float* Wd3     = (const float*)d_in[14];
    const float* Wdec    = (const float*)d_in[15];
    float* out = (float*)d_out;

    (void)in_sizes; (void)n_in; (void)out_size;

    cudaFuncSetAttribute(mol_kernel, cudaFuncAttributeMaxDynamicSharedMemorySize,
                         SM_FLOATS * sizeof(float));

    float *xc, *t, *h, *t2, *zb, *a1, *a2, *z3, *zw, *part;
    __nv_bfloat16 *adj3p, *adj3n, *A3, *B3;
    cudaGetSymbolAddress((void**)&xc,    d_xc);
    cudaGetSymbolAddress((void**)&t,     d_t);
    cudaGetSymbolAddress((void**)&h,     d_h);
    cudaGetSymbolAddress((void**)&t2,    d_t2);
    cudaGetSymbolAddress((void**)&zb,    d_z);
    cudaGetSymbolAddress((void**)&a1,    d_a1);
    cudaGetSymbolAddress((void**)&a2,    d_a2);
    cudaGetSymbolAddress((void**)&z3,    d_z3);
    cudaGetSymbolAddress((void**)&zw,    d_zw);
    cudaGetSymbolAddress((void**)&part,  d_part);
    cudaGetSymbolAddress((void**)&adj3p, d_adj3p);
    cudaGetSymbolAddress((void**)&adj3n, d_adj3n);
    cudaGetSymbolAddress((void**)&A3,    d_A3);
    cudaGetSymbolAddress((void**)&B3,    d_B3);

    const int NE = G * 512;

    // 0) sniff + xc prefix + adjacency bf16 split (reused by steps 5 & 7)
    sniff_kernel<<<1, 256>>>((const int*)enc);
    copyx_kernel<<<(G * 384 + 255) / 256, 256>>>(x);
    convA(adj_pos, adj3p, G, G, G);
    convA(adj_neg, adj3n, G, G, G);

    // 3) molecular GCN -> xc[:, 384:512]
    mol_kernel<<<G, 512, SM_FLOATS * sizeof(float)>>>(mol_adj, enc, tok_emb, Wm1, Wm2);

    // 4) t = xc @ [Wp1 | Wn1]      (Keff 1536; B3 rows: [0,256) and [256,512))
    convA(xc, A3, G, 512, 512);
    convB(Wp1, B3,                        512, 256, 256, 0);
    convB(Wn1, B3 + (long long)256 * 1536, 512, 256, 256, 0);
    tlaunch(mkt(A3, 1536, B3,                         1536, t,       512, G, 256, 0, 1, 1536, 0),
            mkt(A3, 1536, B3 + (long long)256 * 1536, 1536, t + 256, 512, G, 256, 0, 1, 1536, 0), 2);

    // 5) h = relu(adj @ t)         (Keff 9120, split-K 3; branch stride 256*9120)
    convB(t,       B3,                        G, 256, 512, 0);
    convB(t + 256, B3 + (long long)256 * 9120, G, 256, 512, 0);
    tlaunch(mkt(adj3p, K3ADJ, B3,                         9120, part,       512, G, 256, 0, 3, 3040, NE),
            mkt(adj3n, K3ADJ, B3 + (long long)256 * 9120, 9120, part + 256, 512, G, 256, 0, 3, 3040, NE), 2);
    reduce_kernel<<<(NE + 255) / 256, 256>>>(h, NE, 1);

    // 6) t2 = h @ [Wp2 | Wn2]      (Keff 768)
    convA(h,       A3,                      G, 256, 512);
    convA(h + 256, A3 + (long long)G * 768, G, 256, 512);
    convB(Wp2, B3,                       256, 256, 256, 0);
    convB(Wn2, B3 + (long long)256 * 768, 256, 256, 256, 0);
    tlaunch(mkt(A3,                      768, B3,                        768, t2,       512, G, 256, 0, 1, 768, 0),
            mkt(A3 + (long long)G * 768, 768, B3 + (long long)256 * 768, 768, t2 + 256, 512, G, 256, 0, 1, 768, 0), 2);

    // 7) z = adj @ t2
    convB(t2,       B3,                        G, 256, 512, 0);
    convB(t2 + 256, B3 + (long long)256 * 9120, G, 256, 512, 0);
    tlaunch(mkt(adj3p, K3ADJ, B3,                         9120, part,       512, G, 256, 0, 3, 3040, NE),
            mkt(adj3n, K3ADJ, B3 + (long long)256 * 9120, 9120, part + 256, 512, G, 256, 0, 3, 3040, NE), 2);
    reduce_kernel<<<(NE + 255) / 256, 256>>>(zb, NE, 0);

    // 8) a1 = relu(z @ Wd1)        (Keff 1536)
    convA(zb, A3, G, 512, 512);
    convB(Wd1, B3, 512, 256, 256, 0);
    {
        TG p = mkt(A3, 1536, B3, 1536, a1, 256, G, 256, 1, 1, 1536, 0);
        tlaunch(p, p, 1);
    }

    // 9) a2 = relu(a1 @ Wd2)       (Keff 768, N=512)
    convA(a1, A3, G, 256, 256);
    convB(Wd2, B3, 256, 512, 512, 0);
    {
        TG p = mkt(A3, 768, B3, 768, a2, 512, G, 512, 1, 1, 768, 0);
        tlaunch(p, p, 1);
    }

    // 10) z3 = a2 @ Wd3            (Keff 1536)
    convA(a2, A3, G, 512, 512);
    convB(Wd3, B3, 512, 256, 256, 0);
    {
        TG p = mkt(A3, 1536, B3, 1536, z3, 256, G, 256, 0, 1, 1536, 0);
        tlaunch(p, p, 1);
    }

    // 11) zw = z3 @ Wdec           (Keff 768)
    convA(z3, A3, G, 256, 256);
    convB(Wdec, B3, 256, 256, 256, 0);
    {
        TG p = mkt(A3, 768, B3, 768, zw, 256, G, 256, 0, 1, 768, 0);
        tlaunch(p, p, 1);
    }

    // 12) out = zw @ z3^T          (Keff 768, N=3040)
    convA(zw, A3, G, 256, 256);
    convB(z3, B3, 256, G, 256, 1);
    {
        TG p = mkt(A3, 768, B3, 768, out, G, G, G, 0, 1, 768, 0);
        tlaunch(p, p, 1);
    }
}

// round 11
// speedup vs baseline: 1.1737x; 1.0171x over previous
#include <cuda_runtime.h>
#include <cuda_bf16.h>
#include <cstdint>

// ---------------- problem constants ----------------
#define G    3040
#define ATM  100
#define NTOK 43
#define FS   75
#define HS   128
#define H1S  128
#define NF   512
#define NH   256
#define DH   256
#define K3ADJ (3*G)          // 9120

// ---------------- device scratch (static, allowed) ----------------
__device__ float d_xc  [G * NF];
__device__ float d_t   [G * 512];
__device__ float d_h   [G * 512];
__device__ float d_t2  [G * 512];
__device__ float d_z   [G * 512];
__device__ float d_a1  [G * 256];
__device__ float d_a2  [G * 512];
__device__ float d_z3  [G * 256];
__device__ float d_zw  [G * 256];
__device__ float d_part[3 * G * 512];     // split-K partials (max 6 x G*256 = 3 x G*512)
__device__ __nv_bfloat16 d_adj3p[(size_t)G * K3ADJ];
__device__ __nv_bfloat16 d_adj3n[(size_t)G * K3ADJ];
__device__ __nv_bfloat16 d_A3[(size_t)G * 1536];
__device__ __nv_bfloat16 d_B3[(size_t)9120 * 512];
__device__ int   d_is64;

// ---------------- dtype sniff for encoded_drug ----------------
__global__ void sniff_kernel(const int* __restrict__ enc) {
    __shared__ int any;
    if (threadIdx.x == 0) any = 0;
    __syncthreads();
    int seen = 0;
    for (int i = threadIdx.x; i < 4096; i += 256)
        if (enc[2 * i + 1] != 0) seen = 1;
    if (seen) atomicOr(&any, 1);
    __syncthreads();
    if (threadIdx.x == 0) d_is64 = (any == 0) ? 1 : 0;
}

// ---------------- copy x into xc[:, 0:384] ----------------
__global__ void copyx_kernel(const float* __restrict__ x) {
    int i = blockIdx.x * 256 + threadIdx.x;
    if (i < G * 384) {
        int g = i / 384, c = i - g * 384;
        d_xc[g * NF + c] = x[i];
    }
}

// ---------------- split-K reduce (+optional relu), generic slice count ----
__global__ void reduce_kernel(float* __restrict__ out, int n, int relu, int kspl) {
    int i = blockIdx.x * 256 + threadIdx.x;
    if (i < n) {
        float v = 0.0f;
        for (int s = 0; s < kspl; s++) v += d_part[(long long)s * n + i];
        out[i] = relu ? fmaxf(v, 0.0f) : v;
    }
}

// ---------------- bf16 split conversions ----------------
// K-expansion: source k = 16*q + r maps to slots 48q+r, 48q+16+r, 48q+32+r.
// A slots: (hi, hi, lo)    B slots: (hi, lo, hi)
// => hi*hi + hi*lo + lo*hi  (lo*lo dropped, ~2^-18 relative)
// A3 layout: [M][Keff] row-major.   B3 layout: [N][Keff] K-MAJOR (transposed).

__global__ void convA_kernel(const float* __restrict__ src, __nv_bfloat16* __restrict__ dst,
                             int M, int K, int lda) {
    long long idx = (long long)blockIdx.x * 256 + threadIdx.x;
    if (idx >= (long long)M * K) return;
    int m = (int)(idx / K), k = (int)(idx - (long long)m * K);
    float a = src[(long long)m * lda + k];
    __nv_bfloat16 hi = __float2bfloat16(a);
    __nv_bfloat16 lo = __float2bfloat16(a - __bfloat162float(hi));
    int q = k >> 4, r = k & 15;
    long long base = (long long)m * (3LL * K) + 48 * q + r;
    dst[base] = hi; dst[base + 16] = hi; dst[base + 32] = lo;
}

// dst[n][slot(k)]  with row pitch 3K
__global__ void convB_kernel(const float* __restrict__ src, __nv_bfloat16* __restrict__ dst,
                             int K, int N, int lds, int trans) {
    long long idx = (long long)blockIdx.x * 256 + threadIdx.x;
    if (idx >= (long long)K * N) return;
    int k = (int)(idx / N), n = (int)(idx - (long long)k * N);
    float b = trans ? src[(long long)n * lds + k] : src[(long long)k * lds + n];
    __nv_bfloat16 hi = __float2bfloat16(b);
    __nv_bfloat16 lo = __float2bfloat16(b - __bfloat162float(hi));
    int q = k >> 4, r = k & 15;
    long long base = (long long)n * (3LL * K) + 48 * q + r;
    dst[base] = hi; dst[base + 16] = lo; dst[base + 32] = hi;
}

// ---------------- molecular GCN (unchanged, known-good from R5) ----------------
#define SM_ADJ  0
#define SM_W    10100
#define SM_P    26484
#define SM_Q    31988
#define SM_E    37492
#define SM_C    40720
#define SM_D    47120
#define SM_TOK  53520
#define SM_FLOATS 53624

template<int RPW, bool DOMAX>
__device__ __forceinline__ void tile_mm(const float* __restrict__ Xs, int ldx,
                                        const float* __restrict__ Ws,
                                        int K, int Mrows,
                                        float* __restrict__ Out,
                                        float4& mx)
{
    const int lane = threadIdx.x & 31;
    const int warp = threadIdx.x >> 5;
    const int r0 = warp * RPW;

    int xoff[RPW];
#pragma unroll
    for (int i = 0; i < RPW; i++) {
        int rr = r0 + i;
        if (rr >= Mrows) rr = Mrows - 1;
        xoff[i] = rr * ldx;
    }

    float acc[RPW][4];
#pragma unroll
    for (int i = 0; i < RPW; i++)
        acc[i][0] = acc[i][1] = acc[i][2] = acc[i][3] = 0.0f;

    const float* wbase = Ws + lane * 4;
#pragma unroll 4
    for (int h = 0; h < K; h++) {
        float4 wv = *(const float4*)(wbase + h * 128);
#pragma unroll
        for (int i = 0; i < RPW; i++) {
            float xv = Xs[xoff[i] + h];
            acc[i][0] = fmaf(xv, wv.x, acc[i][0]);
            acc[i][1] = fmaf(xv, wv.y, acc[i][1]);
            acc[i][2] = fmaf(xv, wv.z, acc[i][2]);
            acc[i][3] = fmaf(xv, wv.w, acc[i][3]);
        }
    }

    if (DOMAX) {
#pragma unroll
        for (int i = 0; i < RPW; i++) {
            mx.x = fmaxf(mx.x, acc[i][0]);
            mx.y = fmaxf(mx.y, acc[i][1]);
            mx.z = fmaxf(mx.z, acc[i][2]);
            mx.w = fmaxf(mx.w, acc[i][3]);
        }
    } else {
#pragma unroll
        for (int i = 0; i < RPW; i++) {
            if (r0 + i < Mrows) {
                *(float4*)(Out + (r0 + i) * 128 + lane * 4) =
                    make_float4(acc[i][0], acc[i][1], acc[i][2], acc[i][3]);
            }
        }
    }
}

__global__ void __launch_bounds__(512, 1)
mol_kernel(const float* __restrict__ mol_adj,
           const void* __restrict__ encv,
           const float* __restrict__ tok_emb,
           const float* __restrict__ Wm1,
           const float* __restrict__ Wm2)
{
    extern __shared__ float sm[];
    float* sAdj = sm + SM_ADJ;
    float* sW   = sm + SM_W;
    float* sP   = sm + SM_P;
    float* sQ   = sm + SM_Q;
    float* sE   = sm + SM_E;
    float* sC   = sm + SM_C;
    float* sD   = sm + SM_D;
    int*   stok = (int*)(sm + SM_TOK);

    const int g = blockIdx.x;
    const int tid = threadIdx.x;
    const int lane = tid & 31, warp = tid >> 5;
    const int is64 = d_is64;

    if (tid < ATM) {
        const int* e = (const int*)encv;
        stok[tid] = is64 ? e[2 * (g * ATM + tid)] : e[g * ATM + tid];
    }
    for (int idx = tid; idx < ATM * ATM; idx += 512) {
        int a = idx / ATM, b = idx - a * ATM;
        sAdj[b * 101 + a] = mol_adj[g * (ATM * ATM) + idx];
    }
    for (int idx = tid; idx < NTOK * FS; idx += 512) sE[idx] = tok_emb[idx];
    for (int idx = tid; idx < FS * HS; idx += 512) sW[idx] = Wm1[g * (FS * HS) + idx];
    for (int idx = tid; idx < ATM * 64; idx += 512) sC[idx] = 0.0f;
    __syncthreads();

    if (tid < 400) {
        int b = tid >> 2, q = tid & 3;
        const float* arow = sAdj + b * 101;
        float* crow = sC + b * 64;
        for (int a = q * 25; a < q * 25 + 25; a++)
            atomicAdd(&crow[stok[a]], arow[a]);
    }
    __syncthreads();

    float4 dummy = make_float4(0, 0, 0, 0);

    tile_mm<3, false>(sE, FS, sW, FS, NTOK, sP, dummy);
    __syncthreads();

    for (int idx = tid; idx < HS * H1S; idx += 512) sW[idx] = Wm2[g * (HS * H1S) + idx];
    __syncthreads();

    tile_mm<3, false>(sP, 128, sW, HS, NTOK, sQ, dummy);
    __syncthreads();

    {
        const int r0 = warp * 7;
        float ac0[7], ac1[7];
#pragma unroll
        for (int i = 0; i < 7; i++) { ac0[i] = 0.0f; ac1[i] = 0.0f; }
        int roff[7];
#pragma unroll
        for (int i = 0; i < 7; i++) {
            int rr = r0 + i; if (rr >= ATM) rr = ATM - 1;
            roff[i] = rr * 101;
        }
        for (int a = 0; a < ATM; a++) {
            float c0 = sC[a * 64 + lane];
            float c1 = sC[a * 64 + 32 + lane];
#pragma unroll
            for (int i = 0; i < 7; i++) {
                float av = sAdj[roff[i] + a];
                ac0[i] = fmaf(av, c0, ac0[i]);
                ac1[i] = fmaf(av, c1, ac1[i]);
            }
        }
#pragma unroll
        for (int i = 0; i < 7; i++) {
            if (r0 + i < ATM) {
                sD[(r0 + i) * 64 + lane] = ac0[i];
                sD[(r0 + i) * 64 + 32 + lane] = ac1[i];
            }
        }
    }
    __syncthreads();

    float4 mx = make_float4(-3.4e38f, -3.4e38f, -3.4e38f, -3.4e38f);
    tile_mm<7, true>(sD, 64, sQ, NTOK, ATM, nullptr, mx);
    __syncthreads();

    *(float4*)(sW + warp * 128 + lane * 4) = mx;
    __syncthreads();
    if (tid < 128) {
        float m = sW[tid];
#pragma unroll
        for (int w = 1; w < 16; w++) m = fmaxf(m, sW[w * 128 + tid]);
        d_xc[g * NF + 384 + tid] = m;
    }
}

// ---------------- bf16 tensor-core GEMM (mma.sync m16n8k16) ----------------
// A [M][Keff] row-major, B [N][Keff] K-major (both staged identically).
// ldmatrix.x4 fragment loads (conflict-free at pitch 40).
// Tiles 128x128x32, 256 threads, 8 warps (2x4), each warp 64x32.
struct TG {
    const __nv_bfloat16* A; const __nv_bfloat16* B; float* C;
    int M, N, lda, ldb, ldc;      // lda/ldb in bf16 units (row pitch = Keff)
    int relu, kspl, Kc;
    long long pstride;
};

#define TPITCH 40                 // bf16 units per staged row (80 B)
#define TSTG   (128 * TPITCH)     // 5120 per operand

__global__ void __launch_bounds__(256, 2)
tgemm(TG P0, TG P1)
{
    __shared__ __nv_bfloat16 As[TSTG];
    __shared__ __nv_bfloat16 Bs[TSTG];

    const int z = blockIdx.z;
    TG p = (z >= P0.kspl) ? P1 : P0;
    const int slice = (z >= P0.kspl) ? (z - P0.kspl) : z;
    const int k0 = slice * p.Kc;
    const int niter = p.Kc >> 5;
    float* Cp = p.C + (long long)slice * p.pstride;

    const int t = threadIdx.x;
    const int m0 = blockIdx.y * 128, n0 = blockIdx.x * 128;

    // staging maps (identical for A and B): row = t>>1, k-half = (t&1)*16,
    // two float4 per operand per thread -> full 128x32 coverage.
    const int sr  = t >> 1;
    const int skq = (t & 1) * 16;
    const long long aoff = (long long)min(m0 + sr, p.M - 1) * p.lda;
    const long long boff = (long long)min(n0 + sr, p.N - 1) * p.ldb;

    float acc[4][4][4];
#pragma unroll
    for (int i = 0; i < 4; i++)
#pragma unroll
        for (int j = 0; j < 4; j++)
#pragma unroll
            for (int q = 0; q < 4; q++) acc[i][j][q] = 0.0f;

    const int lane = t & 31, warp = t >> 5;
    const int wm = warp >> 2, wn = warp & 3;

    // ldmatrix address lanes:
    // A: row = lane&15, k-half = (lane>>4)*8
    const int arow = (lane & 15);
    const int akh  = ((lane >> 4) & 1) * 8;
    // B: n = ((lane>>4)&1)*8 + (lane&7), k-half = ((lane>>3)&1)*8
    const int brow = ((lane >> 4) & 1) * 8 + (lane & 7);
    const int bkh  = ((lane >> 3) & 1) * 8;

    // prefetch first panel
    float4 ra0, ra1, rb0, rb1;
    {
        ra0 = *(const float4*)(p.A + aoff + k0 + skq);
        ra1 = *(const float4*)(p.A + aoff + k0 + skq + 8);
        rb0 = *(const float4*)(p.B + boff + k0 + skq);
        rb1 = *(const float4*)(p.B + boff + k0 + skq + 8);
    }

    for (int it = 0; it < niter; it++) {
        *(float4*)(As + sr * TPITCH + skq)     = ra0;
        *(float4*)(As + sr * TPITCH + skq + 8) = ra1;
        *(float4*)(Bs + sr * TPITCH + skq)     = rb0;
        *(float4*)(Bs + sr * TPITCH + skq + 8) = rb1;
        __syncthreads();

        if (it + 1 < niter) {
            int kn = k0 + (it + 1) * 32;
            ra0 = *(const float4*)(p.A + aoff + kn + skq);
            ra1 = *(const float4*)(p.A + aoff + kn + skq + 8);
            rb0 = *(const float4*)(p.B + boff + kn + skq);
            rb1 = *(const float4*)(p.B + boff + kn + skq + 8);
        }

#pragma unroll
        for (int kk = 0; kk < 32; kk += 16) {
            uint32_t afr[4][4];
#pragma unroll
            for (int mt = 0; mt < 4; mt++) {
                const __nv_bfloat16* aptr =
                    As + (wm * 64 + mt * 16 + arow) * TPITCH + kk + akh;
                uint32_t sa = (uint32_t)__cvta_generic_to_shared(aptr);
                asm volatile(
                    "ldmatrix.sync.aligned.m8n8.x4.shared.b16 {%0,%1,%2,%3}, [%4];\n"
                    : "=r"(afr[mt][0]), "=r"(afr[mt][1]),
                      "=r"(afr[mt][2]), "=r"(afr[mt][3]) : "r"(sa));
            }
            uint32_t bfr[4][2];
#pragma unroll
            for (int ntp = 0; ntp < 2; ntp++) {
                const __nv_bfloat16* bptr =
                    Bs + (wn * 32 + ntp * 16 + brow) * TPITCH + kk + bkh;
                uint32_t sb = (uint32_t)__cvta_generic_to_shared(bptr);
                uint32_t r0, r1, r2, r3;
                asm volatile(
                    "ldmatrix.sync.aligned.m8n8.x4.shared.b16 {%0,%1,%2,%3}, [%4];\n"
                    : "=r"(r0), "=r"(r1), "=r"(r2), "=r"(r3) : "r"(sb));
                bfr[ntp * 2][0] = r0;     bfr[ntp * 2][1] = r1;
                bfr[ntp * 2 + 1][0] = r2; bfr[ntp * 2 + 1][1] = r3;
            }
#pragma unroll
            for (int mt = 0; mt < 4; mt++)
#pragma unroll
                for (int nt = 0; nt < 4; nt++)
                    asm volatile(
                        "mma.sync.aligned.m16n8k16.row.col.f32.bf16.bf16.f32 "
                        "{%0,%1,%2,%3}, {%4,%5,%6,%7}, {%8,%9}, {%0,%1,%2,%3};\n"
                        : "+f"(acc[mt][nt][0]), "+f"(acc[mt][nt][1]),
                          "+f"(acc[mt][nt][2]), "+f"(acc[mt][nt][3])
                        : "r"(afr[mt][0]), "r"(afr[mt][1]),
                          "r"(afr[mt][2]), "r"(afr[mt][3]),
                          "r"(bfr[nt][0]), "r"(bfr[nt][1]));
        }
        __syncthreads();
    }

    // epilogue
    const int grp = lane >> 2, tid4 = lane & 3;
    const int cr = m0 + wm * 64 + grp;
    const int cc = n0 + wn * 32 + tid4 * 2;
#pragma unroll
    for (int mt = 0; mt < 4; mt++) {
        int r0 = cr + mt * 16;
#pragma unroll
        for (int nt = 0; nt < 4; nt++) {
            int c0 = cc + nt * 8;
            if (c0 < p.N) {
                float v0 = acc[mt][nt][0], v1 = acc[mt][nt][1];
                float v2 = acc[mt][nt][2], v3 = acc[mt][nt][3];
                if (p.relu) {
                    v0 = fmaxf(v0, 0.0f); v1 = fmaxf(v1, 0.0f);
                    v2 = fmaxf(v2, 0.0f); v3 = fmaxf(v3, 0.0f);
                }
                if (r0 < p.M) {
                    Cp[(long long)r0 * p.ldc + c0]     = v0;
                    Cp[(long long)r0 * p.ldc + c0 + 1] = v1;
                }
                if (r0 + 8 < p.M) {
                    Cp[(long long)(r0 + 8) * p.ldc + c0]     = v2;
                    Cp[(long long)(r0 + 8) * p.ldc + c0 + 1] = v3;
                }
            }
        }
    }
}

// ---------------- host helpers ----------------
static TG mkt(const __nv_bfloat16* A, int lda, const __nv_bfloat16* B, int ldb,
              float* C, int ldc, int M, int N, int relu,
              int kspl, int Kc, long long pstride)
{
    TG p; p.A = A; p.B = B; p.C = C; p.M = M; p.N = N;
    p.lda = lda; p.ldb = ldb; p.ldc = ldc; p.relu = relu;
    p.kspl = kspl; p.Kc = Kc; p.pstride = pstride;
    return p;
}

static void tlaunch(const TG& p0, const TG& p1, int nbranch)
{
    dim3 grid((p0.N + 127) / 128, (p0.M + 127) / 128, nbranch * p0.kspl);
    tgemm<<<grid, 256>>>(p0, p1);
}

static void convA(const float* src, __nv_bfloat16* dst, int M, int K, int lda) {
    long long n = (long long)M * K;
    convA_kernel<<<(int)((n + 255) / 256), 256>>>(src, dst, M, K, lda);
}
static void convB(const float* src, __nv_bfloat16* dst, int K, int N,
                  int lds, int trans) {
    long long n = (long long)K * N;
    convB_kernel<<<(int)((n + 255) / 256), 256>>>(src, dst, K, N, lds, trans);
}

extern "C" void kernel_launch(void* const* d_in, const int* in_sizes, int n_in,
                              void* d_out, int out_size)
{
    const float* x       = (const float*)d_in[0];
    const float* adj_pos = (const float*)d_in[1];
    const float* adj_neg = (const float*)d_in[2];
    const float* mol_adj = (const float*)d_in[3];
    const void*  enc     = d_in[4];
    const float* tok_emb = (const float*)d_in[5];
    const float* Wm1     = (const float*)d_in[6];
    const float* Wm2     = (const float*)d_in[7];
    const float* Wp1     = (const float*)d_in[8];
    const float* Wp2     = (const float*)d_in[9];
    const float* Wn1     = (const float*)d_in[10];
    const float* Wn2     = (const float*)d_in[11];
    const float* Wd1     = (const float*)d_in[12];
    const float* Wd2     = (const float*)d_in[13];
    const float* Wd3     = (const float*)d_in[14];
    const float* Wdec    = (const float*)d_in[15];
    float* out = (float*)d_out;

    (void)in_sizes; (void)n_in; (void)out_size;

    cudaFuncSetAttribute(mol_kernel, cudaFuncAttributeMaxDynamicSharedMemorySize,
                         SM_FLOATS * sizeof(float));

    float *xc, *t, *h, *t2, *zb, *a1, *a2, *z3, *zw, *part;
    __nv_bfloat16 *adj3p, *adj3n, *A3, *B3;
    cudaGetSymbolAddress((void**)&xc,    d_xc);
    cudaGetSymbolAddress((void**)&t,     d_t);
    cudaGetSymbolAddress((void**)&h,     d_h);
    cudaGetSymbolAddress((void**)&t2,    d_t2);
    cudaGetSymbolAddress((void**)&zb,    d_z);
    cudaGetSymbolAddress((void**)&a1,    d_a1);
    cudaGetSymbolAddress((void**)&a2,    d_a2);
    cudaGetSymbolAddress((void**)&z3,    d_z3);
    cudaGetSymbolAddress((void**)&zw,    d_zw);
    cudaGetSymbolAddress((void**)&part,  d_part);
    cudaGetSymbolAddress((void**)&adj3p, d_adj3p);
    cudaGetSymbolAddress((void**)&adj3n, d_adj3n);
    cudaGetSymbolAddress((void**)&A3,    d_A3);
    cudaGetSymbolAddress((void**)&B3,    d_B3);

    const int NE  = G * 512;                   // full 2-branch slice size
    const int NE1 = G * 256;                   // single-branch N=256 slice size

    // 0) sniff + xc prefix + adjacency bf16 split (reused by steps 5 & 7)
    sniff_kernel<<<1, 256>>>((const int*)enc);
    copyx_kernel<<<(G * 384 + 255) / 256, 256>>>(x);
    convA(adj_pos, adj3p, G, G, G);
    convA(adj_neg, adj3n, G, G, G);

    // 3) molecular GCN -> xc[:, 384:512]
    mol_kernel<<<G, 512, SM_FLOATS * sizeof(float)>>>(mol_adj, enc, tok_emb, Wm1, Wm2);

    // 4) t = xc @ [Wp1 | Wn1]      (Keff 1536, split-K 3 -> 288 CTAs)
    convA(xc, A3, G, 512, 512);
    convB(Wp1, B3,                         512, 256, 256, 0);
    convB(Wn1, B3 + (long long)256 * 1536, 512, 256, 256, 0);
    tlaunch(mkt(A3, 1536, B3,                         1536, part,       512, G, 256, 0, 3, 512, NE),
            mkt(A3, 1536, B3 + (long long)256 * 1536, 1536, part + 256, 512, G, 256, 0, 3, 512, NE), 2);
    reduce_kernel<<<(NE + 255) / 256, 256>>>(t, NE, 0, 3);

    // 5) h = relu(adj @ t)         (Keff 9120, split-K 3 -> 288 CTAs)
    convB(t,       B3,                         G, 256, 512, 0);
    convB(t + 256, B3 + (long long)256 * 9120, G, 256, 512, 0);
    tlaunch(mkt(adj3p, K3ADJ, B3,                         9120, part,       512, G, 256, 0, 3, 3040, NE),
            mkt(adj3n, K3ADJ, B3 + (long long)256 * 9120, 9120, part + 256, 512, G, 256, 0, 3, 3040, NE), 2);
    reduce_kernel<<<(NE + 255) / 256, 256>>>(h, NE, 1, 3);

    // 6) t2 = h @ [Wp2 | Wn2]      (Keff 768, split-K 3 -> 288 CTAs)
    convA(h,       A3,                      G, 256, 512);
    convA(h + 256, A3 + (long long)G * 768, G, 256, 512);
    convB(Wp2, B3,                        256, 256, 256, 0);
    convB(Wn2, B3 + (long long)256 * 768, 256, 256, 256, 0);
    tlaunch(mkt(A3,                      768, B3,                        768, part,       512, G, 256, 0, 3, 256, NE),
            mkt(A3 + (long long)G * 768, 768, B3 + (long long)256 * 768, 768, part + 256, 512, G, 256, 0, 3, 256, NE), 2);
    reduce_kernel<<<(NE + 255) / 256, 256>>>(t2, NE, 0, 3);

    // 7) z = adj @ t2              (Keff 9120, split-K 3)
    convB(t2,       B3,                         G, 256, 512, 0);
    convB(t2 + 256, B3 + (long long)256 * 9120, G, 256, 512, 0);
    tlaunch(mkt(adj3p, K3ADJ, B3,                         9120, part,       512, G, 256, 0, 3, 3040, NE),
            mkt(adj3n, K3ADJ, B3 + (long long)256 * 9120, 9120, part + 256, 512, G, 256, 0, 3, 3040, NE), 2);
    reduce_kernel<<<(NE + 255) / 256, 256>>>(zb, NE, 0, 3);

    // 8) a1 = relu(z @ Wd1)        (Keff 1536, split-K 6 -> 288 CTAs)
    convA(zb, A3, G, 512, 512);
    convB(Wd1, B3, 512, 256, 256, 0);
    {
        TG p = mkt(A3, 1536, B3, 1536, part, 256, G, 256, 0, 6, 256, NE1);
        tlaunch(p, p, 1);
    }
    reduce_kernel<<<(NE1 + 255) / 256, 256>>>(a1, NE1, 1, 6);

    // 9) a2 = relu(a1 @ Wd2)       (Keff 768, N=512, split-K 3 -> 288 CTAs)
    convA(a1, A3, G, 256, 256);
    convB(Wd2, B3, 256, 512, 512, 0);
    {
        TG p = mkt(A3, 768, B3, 768, part, 512, G, 512, 0, 3, 256, NE);
        tlaunch(p, p, 1);
    }
    reduce_kernel<<<(NE + 255) / 256, 256>>>(a2, NE, 1, 3);

    // 10) z3 = a2 @ Wd3            (Keff 1536, split-K 6 -> 288 CTAs)
    convA(a2, A3, G, 512, 512);
    convB(Wd3, B3, 512, 256, 256, 0);
    {
        TG p = mkt(A3, 1536, B3, 1536, part, 256, G, 256, 0, 6, 256, NE1);
        tlaunch(p, p, 1);
    }
    reduce_kernel<<<(NE1 + 255) / 256, 256>>>(z3, NE1, 0, 6);

    // 11) zw = z3 @ Wdec           (Keff 768, split-K 6 -> 288 CTAs)
    convA(z3, A3, G, 256, 256);
    convB(Wdec, B3, 256, 256, 256, 0);
    {
        TG p = mkt(A3, 768, B3, 768, part, 256, G, 256, 0, 6, 128, NE1);
        tlaunch(p, p, 1);
    }
    reduce_kernel<<<(NE1 + 255) / 256, 256>>>(zw, NE1, 0, 6);

    // 12) out = zw @ z3^T          (Keff 768, N=3040 -> 576 CTAs, no split)
    convA(zw, A3, G, 256, 256);
    convB(z3, B3, 256, G, 256, 1);
    {
        TG p = mkt(A3, 768, B3, 768, out, G, G, G, 0, 1, 768, 0);
        tlaunch(p, p, 1);
    }
}